// round 2
// baseline (speedup 1.0000x reference)
#include <cuda_runtime.h>
#include <math.h>

// Problem constants
#define Bv 8
#define Cv 512
#define Sv 2048
#define Lv 8921

// Tiling
#define TL 64    // labels per CTA
#define TS 128   // s positions per CTA tile
#define CK 32    // c chunk
#define ML 8     // labels per thread (one warp = 8 labels x 128 s)
#define NS 4     // s per thread (32 lanes x 4 = 128)

// logits[b,l] = sum_s softmax_s(u[b,l,:])[s] * v[b,l,s] + b_cls[l]
//   u[b,l,s] = sum_c W_attn[l,c] * enc[b,c,s]   (b_attn cancels under softmax)
//   v[b,l,s] = sum_c W_cls [l,c] * enc[b,c,s]
__global__ __launch_bounds__(256, 2)
void hdec_fused_kernel(const float* __restrict__ enc,
                       const float* __restrict__ Wa,
                       const float* __restrict__ Wc,
                       const float* __restrict__ bcls,
                       float* __restrict__ out)
{
    __shared__ float Es [CK][TS];   // encoded tile  [c][s]
    __shared__ float Was[TL][CK];   // W_attn tile   [l][c]
    __shared__ float Wcs[TL][CK];   // W_cls tile    [l][c]

    const int b    = blockIdx.y;
    const int l0   = blockIdx.x * TL;
    const int tid  = threadIdx.x;
    const int lane = tid & 31;
    const int warp = tid >> 5;            // 0..7 -> label group within tile
    const int lrow = warp * ML;           // local label base for this warp
    const int scol = lane * NS;           // local s base for this lane

    const float* encB = enc + (size_t)b * Cv * Sv;

    // running online-softmax state (m replicated across warp; dsum/acc are
    // per-thread partials over this lane's s-columns)
    float m[ML], dsum[ML], acc[ML];
#pragma unroll
    for (int i = 0; i < ML; i++) { m[i] = -INFINITY; dsum[i] = 0.f; acc[i] = 0.f; }

    for (int s0 = 0; s0 < Sv; s0 += TS) {
        // fresh per-chunk GEMM accumulators
        float u[ML][NS], v[ML][NS];
#pragma unroll
        for (int i = 0; i < ML; i++)
#pragma unroll
            for (int j = 0; j < NS; j++) { u[i][j] = 0.f; v[i][j] = 0.f; }

        for (int c0 = 0; c0 < Cv; c0 += CK) {
            // ---- load E tile: CK x TS = 4096 floats = 1024 float4 ----
#pragma unroll
            for (int k = 0; k < 4; k++) {
                int f4  = tid + k * 256;          // 0..1023
                int row = f4 >> 5;                // CK rows, TS/4=32 f4 per row
                int col = f4 & 31;
                float4 val = *reinterpret_cast<const float4*>(
                    encB + (size_t)(c0 + row) * Sv + s0 + col * 4);
                *reinterpret_cast<float4*>(&Es[row][col * 4]) = val;
            }
            // ---- load W tiles: 2 x (TL x CK) = 1024 float4 total ----
#pragma unroll
            for (int k = 0; k < 4; k++) {
                int idx = tid + k * 256;          // 0..1023
                int wsel = idx >> 9;              // 0: W_attn, 1: W_cls
                int r   = idx & 511;              // 0..511 within one W tile
                int l   = r >> 3;                 // 8 float4 per row (CK=32)
                int cf4 = r & 7;
                int gl  = l0 + l;
                float4 val = make_float4(0.f, 0.f, 0.f, 0.f);
                if (gl < Lv) {
                    const float* W = wsel ? Wc : Wa;
                    val = *reinterpret_cast<const float4*>(
                        W + (size_t)gl * Cv + c0 + cf4 * 4);
                }
                if (wsel) *reinterpret_cast<float4*>(&Wcs[l][cf4 * 4]) = val;
                else      *reinterpret_cast<float4*>(&Was[l][cf4 * 4]) = val;
            }
            __syncthreads();

            // ---- FMA inner loop over c ----
#pragma unroll 8
            for (int c = 0; c < CK; c++) {
                float4 e4 = *reinterpret_cast<const float4*>(&Es[c][scol]);
                float e[NS] = {e4.x, e4.y, e4.z, e4.w};
#pragma unroll
                for (int i = 0; i < ML; i++) {
                    float wa = Was[lrow + i][c];
                    float wc = Wcs[lrow + i][c];
#pragma unroll
                    for (int j = 0; j < NS; j++) {
                        u[i][j] = fmaf(wa, e[j], u[i][j]);
                        v[i][j] = fmaf(wc, e[j], v[i][j]);
                    }
                }
            }
            __syncthreads();
        }

        // ---- online softmax update for this s-chunk ----
#pragma unroll
        for (int i = 0; i < ML; i++) {
            float cm = u[i][0];
#pragma unroll
            for (int j = 1; j < NS; j++) cm = fmaxf(cm, u[i][j]);
#pragma unroll
            for (int off = 16; off > 0; off >>= 1)
                cm = fmaxf(cm, __shfl_xor_sync(0xffffffffu, cm, off));
            float mn = fmaxf(m[i], cm);
            float scale = __expf(m[i] - mn);   // 0 on first chunk (m=-inf)
            dsum[i] *= scale;
            acc[i]  *= scale;
#pragma unroll
            for (int j = 0; j < NS; j++) {
                float w = __expf(u[i][j] - mn);
                dsum[i] += w;
                acc[i]  = fmaf(w, v[i][j], acc[i]);
            }
            m[i] = mn;
        }
    }

    // ---- final warp reduction + write ----
#pragma unroll
    for (int i = 0; i < ML; i++) {
        float dt = dsum[i];
        float at = acc[i];
#pragma unroll
        for (int off = 16; off > 0; off >>= 1) {
            dt += __shfl_xor_sync(0xffffffffu, dt, off);
            at += __shfl_xor_sync(0xffffffffu, at, off);
        }
        int gl = l0 + lrow + i;
        if (lane == 0 && gl < Lv)
            out[(size_t)b * Lv + gl] = at / dt + bcls[gl];
    }
}

extern "C" void kernel_launch(void* const* d_in, const int* in_sizes, int n_in,
                              void* d_out, int out_size)
{
    const float* enc   = (const float*)d_in[0];  // (B, C, S)
    const float* Wa    = (const float*)d_in[1];  // (L, C)
    // d_in[2] = b_attn -- cancels under softmax over s, unused
    const float* Wc    = (const float*)d_in[3];  // (L, C)
    const float* bcls  = (const float*)d_in[4];  // (L,)
    float* out = (float*)d_out;                  // (B, L)

    dim3 grid((Lv + TL - 1) / TL, Bv);           // (140, 8)
    hdec_fused_kernel<<<grid, 256>>>(enc, Wa, Wc, bcls, out);
}

// round 7
// speedup vs baseline: 1.1267x; 1.1267x over previous
#include <cuda_runtime.h>
#include <math.h>

// Problem constants
#define Bv 8
#define Cv 512
#define Sv 2048
#define Lv 8921
#define Lpad 8960   // 140 tiles * 64

// Tiling
#define TL 64    // labels per CTA
#define TS 128   // s positions per CTA tile
#define CK 32    // c chunk
#define ML 8     // labels per thread-warp group (4 packed pairs)
#define NS 4     // s per thread

// Transposed weights, [kind][c][l], zero-padded to Lpad labels.
__device__ float WtG[2][Cv][Lpad];

__device__ __forceinline__ void ffma2(unsigned long long& d,
                                      unsigned long long a,
                                      unsigned long long b) {
    asm("fma.rn.f32x2 %0, %1, %2, %0;" : "+l"(d) : "l"(a), "l"(b));
}
__device__ __forceinline__ float f2lo(unsigned long long x) {
    return __uint_as_float((unsigned)(x & 0xffffffffull));
}
__device__ __forceinline__ float f2hi(unsigned long long x) {
    return __uint_as_float((unsigned)(x >> 32));
}

// ---- one-time (per launch) W transpose: W[l][c] -> WtG[kind][c][l] ----
__global__ void transpose_w_kernel(const float* __restrict__ Wa,
                                   const float* __restrict__ Wc)
{
    __shared__ float t[32][33];
    const int kind = blockIdx.z;
    const float* W = kind ? Wc : Wa;
    const int l0 = blockIdx.x * 32;
    const int c0 = blockIdx.y * 32;
    for (int i = threadIdx.y; i < 32; i += 8) {
        int l = l0 + i;
        t[i][threadIdx.x] = (l < Lv) ? W[(size_t)l * Cv + c0 + threadIdx.x] : 0.f;
    }
    __syncthreads();
    for (int i = threadIdx.y; i < 32; i += 8) {
        WtG[kind][c0 + i][l0 + threadIdx.x] = t[threadIdx.x][i];
    }
}

// logits[b,l] = sum_s softmax_s(u[b,l,:])[s] * v[b,l,s] + b_cls[l]
//   u = W_attn @ enc[b],  v = W_cls @ enc[b]   (b_attn cancels under softmax)
__global__ __launch_bounds__(256, 2)
void hdec_fused_kernel(const float* __restrict__ enc,
                       const float* __restrict__ bcls,
                       float* __restrict__ out)
{
    // Ed[c]: 256 floats = [0:128) dup pairs of s0..s63? no: slot q in first half
    // holds (e_{4q}, e_{4q}, e_{4q+1}, e_{4q+1}); second half (e_{4q+2}.., e_{4q+3}..)
    __shared__ float Ed [CK][256];      // 32 KB
    __shared__ float Wts[2][CK][TL];    // 16 KB  (total 48 KB exactly)

    const int b    = blockIdx.y;
    const int l0   = blockIdx.x * TL;
    const int tid  = threadIdx.x;
    const int lane = tid & 31;
    const int warp = tid >> 5;
    const int lrow = warp * ML;         // local label base (8 labels / warp-group)

    const float* encB = enc + (size_t)b * Cv * Sv;

    float m[ML], dsum[ML], acc[ML];
#pragma unroll
    for (int i = 0; i < ML; i++) { m[i] = -INFINITY; dsum[i] = 0.f; acc[i] = 0.f; }

    for (int s0 = 0; s0 < Sv; s0 += TS) {
        // packed accumulators: u2[p][j] = (u[2p][j], u[2p+1][j])
        unsigned long long u2[4][NS], v2[4][NS];
#pragma unroll
        for (int p = 0; p < 4; p++)
#pragma unroll
            for (int j = 0; j < NS; j++) { u2[p][j] = 0ull; v2[p][j] = 0ull; }

        for (int c0 = 0; c0 < Cv; c0 += CK) {
            // ---- fill E tile (duplicated pairs): 1024 float4 reads ----
#pragma unroll
            for (int k = 0; k < 4; k++) {
                int f4  = tid + k * 256;          // 0..1023
                int row = f4 >> 5;                // c row (32 rows)
                int col = f4 & 31;                // s-group (4 s each)
                float4 ev = *reinterpret_cast<const float4*>(
                    encB + (size_t)(c0 + row) * Sv + s0 + col * 4);
                float4 d0 = make_float4(ev.x, ev.x, ev.y, ev.y);
                float4 d1 = make_float4(ev.z, ev.z, ev.w, ev.w);
                *reinterpret_cast<float4*>(&Ed[row][col * 4])       = d0;
                *reinterpret_cast<float4*>(&Ed[row][128 + col * 4]) = d1;
            }
            // ---- fill W tiles from pre-transposed global: coalesced, dense STS ----
#pragma unroll
            for (int k = 0; k < 4; k++) {
                int idx  = tid + k * 256;         // 0..1023
                int wsel = idx >> 9;              // 0: attn, 1: cls
                int r    = idx & 511;
                int row  = r >> 4;                // c row (32 rows, 16 f4/row)
                int lf4  = r & 15;
                float4 wv = *reinterpret_cast<const float4*>(
                    &WtG[wsel][c0 + row][l0 + lf4 * 4]);
                *reinterpret_cast<float4*>(&Wts[wsel][row][lf4 * 4]) = wv;
            }
            __syncthreads();

            // ---- packed FFMA2 inner loop ----
#pragma unroll 4
            for (int c = 0; c < CK; c++) {
                ulonglong2 e01 = *reinterpret_cast<const ulonglong2*>(&Ed[c][lane << 2]);
                ulonglong2 e23 = *reinterpret_cast<const ulonglong2*>(&Ed[c][128 + (lane << 2)]);
                ulonglong2 wa01 = *reinterpret_cast<const ulonglong2*>(&Wts[0][c][lrow]);
                ulonglong2 wa23 = *reinterpret_cast<const ulonglong2*>(&Wts[0][c][lrow + 4]);
                ulonglong2 wc01 = *reinterpret_cast<const ulonglong2*>(&Wts[1][c][lrow]);
                ulonglong2 wc23 = *reinterpret_cast<const ulonglong2*>(&Wts[1][c][lrow + 4]);
                unsigned long long ed[NS] = {e01.x, e01.y, e23.x, e23.y};
                unsigned long long wp[4]  = {wa01.x, wa01.y, wa23.x, wa23.y};
                unsigned long long wq[4]  = {wc01.x, wc01.y, wc23.x, wc23.y};
#pragma unroll
                for (int p = 0; p < 4; p++)
#pragma unroll
                    for (int j = 0; j < NS; j++) {
                        ffma2(u2[p][j], wp[p], ed[j]);
                        ffma2(v2[p][j], wq[p], ed[j]);
                    }
            }
            __syncthreads();
        }

        // ---- online softmax update for this s-chunk ----
#pragma unroll
        for (int p = 0; p < 4; p++) {
#pragma unroll
            for (int h = 0; h < 2; h++) {
                const int i = 2 * p + h;
                float uj[NS], vj[NS];
#pragma unroll
                for (int j = 0; j < NS; j++) {
                    uj[j] = h ? f2hi(u2[p][j]) : f2lo(u2[p][j]);
                    vj[j] = h ? f2hi(v2[p][j]) : f2lo(v2[p][j]);
                }
                float cm = uj[0];
#pragma unroll
                for (int j = 1; j < NS; j++) cm = fmaxf(cm, uj[j]);
#pragma unroll
                for (int off = 16; off > 0; off >>= 1)
                    cm = fmaxf(cm, __shfl_xor_sync(0xffffffffu, cm, off));
                float mn = fmaxf(m[i], cm);
                float scale = __expf(m[i] - mn);   // 0 on first chunk
                dsum[i] *= scale;
                acc[i]  *= scale;
#pragma unroll
                for (int j = 0; j < NS; j++) {
                    float w = __expf(uj[j] - mn);
                    dsum[i] += w;
                    acc[i]  = fmaf(w, vj[j], acc[i]);
                }
                m[i] = mn;
            }
        }
    }

    // ---- final warp reduction + write ----
#pragma unroll
    for (int i = 0; i < ML; i++) {
        float dt = dsum[i];
        float at = acc[i];
#pragma unroll
        for (int off = 16; off > 0; off >>= 1) {
            dt += __shfl_xor_sync(0xffffffffu, dt, off);
            at += __shfl_xor_sync(0xffffffffu, at, off);
        }
        int gl = l0 + lrow + i;
        if (lane == 0 && gl < Lv)
            out[(size_t)b * Lv + gl] = at / dt + bcls[gl];
    }
}

extern "C" void kernel_launch(void* const* d_in, const int* in_sizes, int n_in,
                              void* d_out, int out_size)
{
    const float* enc  = (const float*)d_in[0];  // (B, C, S)
    const float* Wa   = (const float*)d_in[1];  // (L, C)
    // d_in[2] = b_attn -- cancels under softmax over s, unused
    const float* Wc   = (const float*)d_in[3];  // (L, C)
    const float* bcls = (const float*)d_in[4];  // (L,)
    float* out = (float*)d_out;                 // (B, L)

    dim3 tgrid(Lpad / 32, Cv / 32, 2);          // (280, 16, 2)
    transpose_w_kernel<<<tgrid, dim3(32, 8)>>>(Wa, Wc);

    dim3 grid(Lpad / TL, Bv);                   // (140, 8)
    hdec_fused_kernel<<<grid, 256>>>(enc, bcls, out);
}